// round 7
// baseline (speedup 1.0000x reference)
#include <cuda_runtime.h>
#include <cuda_bf16.h>
#include <cstdint>

// OccupancyGridForestAS: 4.19M points, 8x8x8 block lookup -> 64 trees of 64^3 voxels.
//
// inputs (metadata order):
//   d_in[0]: pts            float32 [N_PTS, 3]
//   d_in[1]: occ_val_grid   float32 [64, 64, 64, 64]
//   d_in[2]: block_lookup   int32   [8, 8, 8]
// output: float32 [N_PTS]
//
// R7: persistent kernel + 4-stage cp.async ring staging the pts stream into
// smem. Stream-load latency comes off the warp scoreboard (async copy engine),
// so the only remaining exposed LDG latency is the 2 grid gathers per thread.
// Cache policy reverted to R5's proven config: cp.async.cg (L1 bypass) for the
// stream, __ldcg gathers, __stcs output.

#define RES       64
#define LDIM      8
#define NTHREADS  256
#define TILE_PTS  512                       // 2 pts/thread per tile
#define TILE_FLT  (TILE_PTS * 3)            // 1536 floats
#define TILE_B    (TILE_FLT * 4)            // 6144 bytes
#define CP16      (TILE_B / 16)             // 384 16B chunks
#define STAGES    4
#define NBLOCKS   (148 * 8)

__device__ __forceinline__ uint32_t smem_u32(const void* p) {
    return (uint32_t)__cvta_generic_to_shared(p);
}

__global__ void __launch_bounds__(NTHREADS)
occ_forest_kernel(const float* __restrict__ pts,
                  const float* __restrict__ occ,
                  const int*   __restrict__ lut,
                  float2*      __restrict__ out2,
                  int ntiles)
{
    __shared__ __align__(16) float s_pts[STAGES][TILE_FLT];
    __shared__ int s_lut[LDIM * LDIM * LDIM];

    const int tid  = threadIdx.x;
    const int nblk = gridDim.x;

    s_lut[tid]       = lut[tid];
    s_lut[tid + 256] = lut[tid + 256];
    // (visibility covered by the __syncthreads inside the pipeline below)

    // ---- preload STAGES-1 tiles ----
#pragma unroll
    for (int k = 0; k < STAGES - 1; k++) {
        int tile = blockIdx.x + k * nblk;
        if (tile < ntiles) {
            const char* gsrc = (const char*)pts + (size_t)tile * TILE_B;
            uint32_t sdst = smem_u32(&s_pts[k][0]);
#pragma unroll
            for (int i = tid; i < CP16; i += NTHREADS) {
                asm volatile("cp.async.cg.shared.global [%0], [%1], 16;\n"
                             :: "r"(sdst + i * 16), "l"(gsrc + i * 16));
            }
        }
        asm volatile("cp.async.commit_group;\n");
    }

    // ---- main loop ----
    int it = 0;
    for (int tile = blockIdx.x; tile < ntiles; tile += nblk, it++) {
        asm volatile("cp.async.wait_group %0;\n" :: "n"(STAGES - 2));
        __syncthreads();

        const int st = it & (STAGES - 1);
        const float* sp = &s_pts[st][6 * tid];
        float2 a = *(const float2*)(sp + 0);
        float2 b = *(const float2*)(sp + 2);
        float2 c = *(const float2*)(sp + 4);

        float px[2] = {a.x, b.y};
        float py[2] = {a.y, c.x};
        float pz[2] = {b.x, c.y};

        int  idx[2];
        bool valid[2];

#pragma unroll
        for (int i = 0; i < 2; i++) {
            float x = px[i], y = py[i], z = pz[i];

            int bx = (int)floorf(x);
            int by = (int)floorf(y);
            int bz = (int)floorf(z);

            bool in_dom = (bx >= 0) & (bx < LDIM) &
                          (by >= 0) & (by < LDIM) &
                          (bz >= 0) & (bz < LDIM);

            int cx = min(max(bx, 0), LDIM - 1);
            int cy = min(max(by, 0), LDIM - 1);
            int cz = min(max(bz, 0), LDIM - 1);

            int bidx = s_lut[cx * (LDIM * LDIM) + cy * LDIM + cz];
            valid[i] = in_dom && (bidx >= 0);

            // Bit-exact reference float sequence:
            //   block_x = 2*(p - bcs) - 1 ; vox = floor((block_x*0.5+0.5)*RES)
            // valid => x-cx in [0,1) => vox in [0,63], clamps elided.
            float bxf = 2.0f * (x - (float)cx) - 1.0f;
            float byf = 2.0f * (y - (float)cy) - 1.0f;
            float bzf = 2.0f * (z - (float)cz) - 1.0f;

            int vx = (int)floorf((bxf * 0.5f + 0.5f) * (float)RES);
            int vy = (int)floorf((byf * 0.5f + 0.5f) * (float)RES);
            int vz = (int)floorf((bzf * 0.5f + 0.5f) * (float)RES);

            idx[i] = bidx * (RES * RES * RES) + vx * (RES * RES) + vy * RES + vz;
        }

        float r0 = valid[0] ? __ldcg(&occ[idx[0]]) : 0.0f;
        float r1 = valid[1] ? __ldcg(&occ[idx[1]]) : 0.0f;

        float2 o; o.x = r0; o.y = r1;
        __stcs(&out2[(size_t)tile * NTHREADS + tid], o);

        __syncthreads();   // everyone done reading slot before refill

        int ntile = tile + (STAGES - 1) * nblk;
        if (ntile < ntiles) {
            const char* gsrc = (const char*)pts + (size_t)ntile * TILE_B;
            uint32_t sdst = smem_u32(&s_pts[(it + STAGES - 1) & (STAGES - 1)][0]);
#pragma unroll
            for (int i = tid; i < CP16; i += NTHREADS) {
                asm volatile("cp.async.cg.shared.global [%0], [%1], 16;\n"
                             :: "r"(sdst + i * 16), "l"(gsrc + i * 16));
            }
        }
        asm volatile("cp.async.commit_group;\n");
    }
}

extern "C" void kernel_launch(void* const* d_in, const int* in_sizes, int n_in,
                              void* d_out, int out_size)
{
    const float* pts = (const float*)d_in[0];
    const float* occ = (const float*)d_in[1];
    const int*   lut = (const int*)d_in[2];
    float2*      out = (float2*)d_out;

    int n_pts  = in_sizes[0] / 3;          // 4,194,304
    int ntiles = n_pts / TILE_PTS;         // 8192

    occ_forest_kernel<<<NBLOCKS, NTHREADS>>>(pts, occ, lut, out, ntiles);
}

// round 8
// speedup vs baseline: 1.4320x; 1.4320x over previous
#include <cuda_runtime.h>
#include <cuda_bf16.h>

// OccupancyGridForestAS: 4.19M points, 8x8x8 block lookup -> 64 trees of 64^3 voxels.
//
// inputs (metadata order):
//   d_in[0]: pts            float32 [N_PTS, 3]
//   d_in[1]: occ_val_grid   float32 [64, 64, 64, 64]
//   d_in[2]: block_lookup   int32   [8, 8, 8]
// output: float32 [N_PTS]
//
// R8: persistent grid-stride (1184 blocks = one full resident wave), flat loop
// (no barriers, no prefetch predicates), 4 pts per thread-iteration:
//   - 3x LDG.128 streaming loads/iter (2x in-flight bytes vs float2 version)
//   - 4 independent __ldcg gathers/iter (2x gather MLP)
//   - fractional last iteration spreads uniformly across SMs (no wave tail)
// Cache policy = proven R5 config (__ldcs stream, __ldcg gather, __stcs out),
// smem lut, clamp-free vox math.

#define RES   64
#define LDIM  8
#define NTHREADS 256
#define NBLOCKS  (148 * 8)

__global__ void __launch_bounds__(NTHREADS)
occ_forest_kernel(const float4* __restrict__ pts4,
                  const float*  __restrict__ occ,
                  const int*    __restrict__ lut,
                  float4*       __restrict__ out4,
                  int nc)                      // number of 4-point chunks
{
    __shared__ int s_lut[LDIM * LDIM * LDIM];  // 512 ints = 2KB
    {
        int tid = threadIdx.x;
        s_lut[tid]       = lut[tid];
        s_lut[tid + 256] = lut[tid + 256];
    }
    __syncthreads();

    const int stride = gridDim.x * blockDim.x;

    for (int t = blockIdx.x * blockDim.x + threadIdx.x; t < nc; t += stride) {
        // 4 points = 12 floats = 3 float4 (coalesced, evict-first in L2)
        float4 a = __ldcs(&pts4[3 * t + 0]);
        float4 b = __ldcs(&pts4[3 * t + 1]);
        float4 c = __ldcs(&pts4[3 * t + 2]);

        float px[4] = {a.x, a.w, b.z, c.y};
        float py[4] = {a.y, b.x, b.w, c.z};
        float pz[4] = {a.z, b.y, c.x, c.w};

        int  idx[4];
        bool valid[4];

        // Phase 1: index math for all 4 points (no cross-point dependencies)
#pragma unroll
        for (int i = 0; i < 4; i++) {
            float x = px[i], y = py[i], z = pz[i];

            int bx = (int)floorf(x);
            int by = (int)floorf(y);
            int bz = (int)floorf(z);

            bool in_dom = (bx >= 0) & (bx < LDIM) &
                          (by >= 0) & (by < LDIM) &
                          (bz >= 0) & (bz < LDIM);

            int cx = min(max(bx, 0), LDIM - 1);
            int cy = min(max(by, 0), LDIM - 1);
            int cz = min(max(bz, 0), LDIM - 1);

            int bidx = s_lut[cx * (LDIM * LDIM) + cy * LDIM + cz];
            valid[i] = in_dom && (bidx >= 0);

            // Bit-exact reference float sequence:
            //   block_x = 2*(p - bcs) - 1 ; vox = floor((block_x*0.5+0.5)*RES)
            // valid => x-cx in [0,1) => vox in [0,63]; clamps elided
            // (invalid points never issue the load).
            float bxf = 2.0f * (x - (float)cx) - 1.0f;
            float byf = 2.0f * (y - (float)cy) - 1.0f;
            float bzf = 2.0f * (z - (float)cz) - 1.0f;

            int vx = (int)floorf((bxf * 0.5f + 0.5f) * (float)RES);
            int vy = (int)floorf((byf * 0.5f + 0.5f) * (float)RES);
            int vz = (int)floorf((bzf * 0.5f + 0.5f) * (float)RES);

            idx[i] = bidx * (RES * RES * RES) + vx * (RES * RES) + vy * RES + vz;
        }

        // Phase 2: 4 independent predicated gathers (L2-only path)
        float r[4];
#pragma unroll
        for (int i = 0; i < 4; i++)
            r[i] = valid[i] ? __ldcg(&occ[idx[i]]) : 0.0f;

        float4 o;
        o.x = r[0]; o.y = r[1]; o.z = r[2]; o.w = r[3];
        __stcs(&out4[t], o);
    }
}

extern "C" void kernel_launch(void* const* d_in, const int* in_sizes, int n_in,
                              void* d_out, int out_size)
{
    const float4* pts4 = (const float4*)d_in[0];
    const float*  occ  = (const float*)d_in[1];
    const int*    lut  = (const int*)d_in[2];
    float4*       out  = (float4*)d_out;

    int n_pts = in_sizes[0] / 3;       // 4,194,304
    int nc    = n_pts / 4;             // 1,048,576 4-point chunks

    occ_forest_kernel<<<NBLOCKS, NTHREADS>>>(pts4, occ, lut, out, nc);
}